// round 14
// baseline (speedup 1.0000x reference)
#include <cuda_runtime.h>
#include <cuda_fp16.h>
#include <math.h>
#include <stdint.h>

#define BBATCH 16
#define NPTS   4096
#define THREADS 512
#define SPLIT 2
#define HALF_PTS (NPTS / SPLIT)            // 2048 targets per block
#define ROWS_PER_BLOCK 2048                // 16 warps x 128 rows
#define ROW_TILES (NPTS / ROWS_PER_BLOCK)  // 2
#define NPAIRS (2 * BBATCH * ROW_TILES)    // 64 merge pairs
#define GSIZE 64
#define NGROUPS (HALF_PTS / GSIZE)         // 32
#define EPSF 1e-12f

// Dynamic smem layout (bytes)
#define SM_SX 0
#define SM_SY (SM_SX + HALF_PTS * 4)
#define SM_SZ (SM_SY + HALF_PTS * 4)
#define SM_SW (SM_SZ + HALF_PTS * 4)
#define SM_B16 (SM_SW + HALF_PTS * 4)      // 2048 x 16B fp16 target rows
#define SM_MASK (SM_B16 + HALF_PTS * 16)   // 2048 x u32 row masks
#define SM_TOTAL (SM_MASK + ROWS_PER_BLOCK * 4)

__device__ float g_vmin[2 * BBATCH * SPLIT * NPTS];
__device__ int   g_vidx[2 * BBATCH * SPLIT * NPTS];
__device__ unsigned int g_pair[NPAIRS];
__device__ float g_partials[NPAIRS];
__device__ unsigned int g_done = 0;

__device__ __forceinline__ float ldcg_f(const float* p) {
    float v; asm volatile("ld.global.cg.f32 %0, [%1];" : "=f"(v) : "l"(p)); return v;
}
__device__ __forceinline__ int ldcg_i(const int* p) {
    int v; asm volatile("ld.global.cg.s32 %0, [%1];" : "=r"(v) : "l"(p)); return v;
}
__device__ __forceinline__ uint32_t packh2(__half lo, __half hi) {
    __half2 h = __halves2half2(lo, hi);
    return *reinterpret_cast<uint32_t*>(&h);
}

// blockIdx.x = tile*SPLIT + half (0..3), y = batch, z = dir.
__global__ __launch_bounds__(THREADS, 1)
void chamfer_mma_kernel(const float* __restrict__ kp1,
                        const float* __restrict__ kp2,
                        const float* __restrict__ sig1,
                        const float* __restrict__ sig2,
                        float* __restrict__ out)
{
    const int tile = blockIdx.x >> 1;
    const int half = blockIdx.x & 1;
    const int b    = blockIdx.y;
    const int dir  = blockIdx.z;
    const float* qk = dir ? kp2 : kp1;
    const float* tk = dir ? kp1 : kp2;

    extern __shared__ char smem[];
    float* sx = (float*)(smem + SM_SX);
    float* sy = (float*)(smem + SM_SY);
    float* sz = (float*)(smem + SM_SZ);
    float* sw = (float*)(smem + SM_SW);
    uint4* b16 = (uint4*)(smem + SM_B16);
    uint32_t* maskbuf = (uint32_t*)(smem + SM_MASK);

    {   // fill fp32 SoA (exact replay) + fp16 B rows {x,y,z,w1,w2,0,0,0}
        const float* tp = tk + (size_t)b * 3 * NPTS + half * HALF_PTS;
        for (int i = threadIdx.x; i < HALF_PTS; i += THREADS) {
            float x = tp[i];
            float y = tp[NPTS + i];
            float z = tp[2 * NPTS + i];
            float w = fmaf(x, x, fmaf(y, y, z * z));
            sx[i] = x; sy[i] = y; sz[i] = z; sw[i] = w;
            // split w so both parts round exactly/tiny in fp16
            float w1 = rintf(w * 4.0f) * 0.25f;   // 0.25 grid: exact in fp16 (w<64)
            float w2 = w - w1;                    // |w2| <= 0.125
            b16[i] = make_uint4(
                packh2(__float2half(x),  __float2half(y)),
                packh2(__float2half(z),  __float2half(w1)),
                packh2(__float2half(w2), __float2half(0.0f)),
                0u);
        }
    }
    __syncthreads();

    const float* qp = qk + (size_t)b * 3 * NPTS;
    const int warp = threadIdx.x >> 5;
    const int lane = threadIdx.x & 31;
    const int gq   = lane >> 2;     // 0..7 (fragment group)
    const int i4   = lane & 3;      // 0..3
    const int warp_row0 = tile * ROWS_PER_BLOCK + warp * 128;
    const float INF = __int_as_float(0x7f800000);

    // Build A fragments: A[r][k] = {-2ax,-2ay,-2az, 1, 1, 0,0,0}
    uint32_t afrag[8][2];
    float maxsum = 0.0f;
    #pragma unroll
    for (int s = 0; s < 8; s++) {
        #pragma unroll
        for (int j = 0; j < 2; j++) {
            int r = warp_row0 + s * 16 + gq + j * 8;
            float x = qp[r], y = qp[NPTS + r], z = qp[2 * NPTS + r];
            maxsum = fmaxf(maxsum, fabsf(x) + fabsf(y) + fabsf(z));
            uint32_t a;
            if (i4 == 0)      a = packh2(__float2half(-2.0f * x), __float2half(-2.0f * y));
            else if (i4 == 1) a = packh2(__float2half(-2.0f * z), __float2half(1.0f));
            else if (i4 == 2) a = packh2(__float2half(1.0f),      __float2half(0.0f));
            else              a = 0u;
            afrag[s][j] = a;
        }
    }
    const float Mt = 0.02f + 0.02f * maxsum;   // >= 2x fp16-input error bound

    float    m[8][2], best[8][2];
    uint32_t mask[8][2];
    #pragma unroll
    for (int s = 0; s < 8; s++)
        #pragma unroll
        for (int j = 0; j < 2; j++) { m[s][j] = INF; best[s][j] = INF; mask[s][j] = 0u; }

    const float z0 = 0.0f;
    const char* bbase = (const char*)b16;
    int n0 = 0;
    for (int gidx = 0; gidx < NGROUPS; gidx++) {
        #pragma unroll
        for (int cc = 0; cc < GSIZE / 8; cc++, n0 += 8) {
            // B fragment: lane reads halves {T[n0+gq][2*i4], [2*i4+1]} (coalesced)
            uint32_t bf = *(const uint32_t*)(bbase + (size_t)(n0 + gq) * 16 + i4 * 4);
            #pragma unroll
            for (int s = 0; s < 8; s++) {
                float d0, d1, d2, d3;
                asm volatile(
                    "mma.sync.aligned.m16n8k8.row.col.f32.f16.f16.f32 "
                    "{%0,%1,%2,%3}, {%4,%5}, {%6}, {%7,%8,%9,%10};"
                    : "=f"(d0), "=f"(d1), "=f"(d2), "=f"(d3)
                    : "r"(afrag[s][0]), "r"(afrag[s][1]), "r"(bf),
                      "f"(z0), "f"(z0), "f"(z0), "f"(z0));
                m[s][0] = fminf(m[s][0], fminf(d0, d1));
                m[s][1] = fminf(m[s][1], fminf(d2, d3));
            }
        }
        // group end: lane-local margin test (over-inclusive across lanes is safe)
        #pragma unroll
        for (int s = 0; s < 8; s++) {
            #pragma unroll
            for (int j = 0; j < 2; j++) {
                if (m[s][j] <= best[s][j] + Mt) mask[s][j] |= (1u << gidx);
                best[s][j] = fminf(best[s][j], m[s][j]);
                m[s][j] = INF;
            }
        }
    }

    // Combine masks across the 4 lanes covering each row; stash per-row mask.
    #pragma unroll
    for (int s = 0; s < 8; s++) {
        #pragma unroll
        for (int j = 0; j < 2; j++) {
            uint32_t mk = mask[s][j];
            mk |= __shfl_xor_sync(0xffffffffu, mk, 1);
            mk |= __shfl_xor_sync(0xffffffffu, mk, 2);
            if (i4 == 0) maskbuf[warp * 128 + s * 16 + j * 8 + gq] = mk;
        }
    }
    __syncwarp();

    // Exact replay: lane handles warp-rows lane, lane+32, lane+64, lane+96.
    const size_t sb = (((size_t)(dir * BBATCH + b)) * SPLIT + half) * NPTS;
    #pragma unroll
    for (int c = 0; c < 4; c++) {
        const int rl  = lane + 32 * c;
        const int row = warp_row0 + rl;
        uint32_t mk = maskbuf[warp * 128 + rl];
        float nx = -2.0f * qp[row];
        float ny = -2.0f * qp[NPTS + row];
        float nz = -2.0f * qp[2 * NPTS + row];
        float vb = INF;
        int   bi = 0;
        while (mk) {                         // ascending groups -> first-argmin
            int gsel = __ffs(mk) - 1;
            mk &= mk - 1;
            const int base = gsel * GSIZE;
            #pragma unroll 4
            for (int k = 0; k < GSIZE; k++) {
                const int n = base + k;
                float v = fmaf(nx, sx[n], fmaf(ny, sy[n], fmaf(nz, sz[n], sw[n])));
                bi = (v < vb) ? n : bi;      // strict < keeps first index
                vb = fminf(vb, v);
            }
        }
        g_vmin[sb + row] = vb;
        g_vidx[sb + row] = bi + half * HALF_PTS;
    }

    // Pair rendezvous: second finisher merges halves and computes the loss.
    const int pair_id = (dir * BBATCH + b) * ROW_TILES + tile;
    __shared__ int s_second;
    __threadfence();
    __syncthreads();
    if (threadIdx.x == 0)
        s_second = (atomicAdd(&g_pair[pair_id], 1u) == 1);
    __syncthreads();
    if (!s_second) return;
    __threadfence();

    const size_t pm = (((size_t)(dir * BBATCH + b)) * SPLIT) * NPTS;       // half0
    const size_t pm1 = pm + NPTS;                                          // half1
    float acc = 0.0f;
    const float* qs = (dir ? sig2 : sig1) + (size_t)b * NPTS;
    const float* ts = (dir ? sig1 : sig2) + (size_t)b * NPTS;
    #pragma unroll
    for (int r = 0; r < 4; r++) {
        const int mrow = tile * ROWS_PER_BLOCK + threadIdx.x + r * THREADS;
        float v0 = ldcg_f(g_vmin + pm + mrow);
        int   i0 = ldcg_i(g_vidx + pm + mrow);
        float v1 = ldcg_f(g_vmin + pm1 + mrow);
        int   i1 = ldcg_i(g_vidx + pm1 + mrow);
        bool use0 = (v0 <= v1);              // tie -> half0 (lower index first)
        float vmin = use0 ? v0 : v1;
        int   bi   = use0 ? i0 : i1;

        float x = qp[mrow], y = qp[NPTS + mrow], z = qp[2 * NPTS + mrow];
        float sqa = fmaf(x, x, fmaf(y, y, z * z));
        float d2  = vmin + sqa;
        float mind = sqrtf(fmaxf(d2, EPSF));
        float sg = 0.5f * (qs[mrow] + ts[bi]);
        acc += logf(sg) + mind / sg;
    }

    // Block reduction -> per-pair partial (fixed order, deterministic).
    __shared__ float red[THREADS];
    __shared__ int   s_last;
    red[threadIdx.x] = acc;
    __syncthreads();
    #pragma unroll
    for (int s = THREADS / 2; s > 32; s >>= 1) {
        if (threadIdx.x < s) red[threadIdx.x] += red[threadIdx.x + s];
        __syncthreads();
    }
    if (threadIdx.x < 32) {
        float v = red[threadIdx.x] + red[threadIdx.x + 32];
        #pragma unroll
        for (int o = 16; o > 0; o >>= 1)
            v += __shfl_down_sync(0xffffffffu, v, o);
        if (threadIdx.x == 0) {
            g_partials[pair_id] = v;
            g_pair[pair_id] = 0;             // reset for next graph replay
            __threadfence();
            unsigned int old = atomicAdd(&g_done, 1u);
            s_last = (old == NPAIRS - 1);
        }
    }
    __syncthreads();

    if (s_last) {                            // fold the 64 partials
        __threadfence();
        __shared__ double dred[NPAIRS];
        if (threadIdx.x < NPAIRS)
            dred[threadIdx.x] = (double)ldcg_f(g_partials + threadIdx.x);
        __syncthreads();
        for (int s = NPAIRS / 2; s > 0; s >>= 1) {
            if (threadIdx.x < s) dred[threadIdx.x] += dred[threadIdx.x + s];
            __syncthreads();
        }
        if (threadIdx.x == 0) {
            out[0] = (float)(dred[0] * (1.0 / ((double)BBATCH * (double)NPTS)));
            g_done = 0;                      // reset for next graph replay
        }
    }
}

extern "C" void kernel_launch(void* const* d_in, const int* in_sizes, int n_in,
                              void* d_out, int out_size)
{
    (void)in_sizes; (void)n_in; (void)out_size;
    const float* kp1  = (const float*)d_in[0];  // [B, 3, M]
    const float* kp2  = (const float*)d_in[1];  // [B, 3, N]
    const float* sig1 = (const float*)d_in[2];  // [B, M]
    const float* sig2 = (const float*)d_in[3];  // [B, N]
    float* out = (float*)d_out;

    cudaFuncSetAttribute(chamfer_mma_kernel,
                         cudaFuncAttributeMaxDynamicSharedMemorySize, SM_TOTAL);

    dim3 grid(ROW_TILES * SPLIT, BBATCH, 2);    // 4 x 16 x 2 = 128 blocks
    chamfer_mma_kernel<<<grid, THREADS, SM_TOTAL>>>(kp1, kp2, sig1, sig2, out);
}